// round 8
// baseline (speedup 1.0000x reference)
#include <cuda_runtime.h>
#include <cstdint>

// ============================================================================
// DirectionalConv3d on GB300 via mma.sync TF32 (compute_103-safe: no tcgen05).
//   x: [8, 64, 32, 32, 32] fp32; 7 weights [64,64]; out[b,o,n] =
//     sum_d sum_i W_d[o,i] * x[b,i, n+shift_d]   (zero outside domain)
// Pipeline:
//   k_w:     weights -> per-lane B-fragment layout, tf32      (g_bp)
//   k_split: x -> point-major, k-permuted tf32 rows (256B/pt) (g_xs)
//   k_gemm:  persistent fused 7-direction GEMM, m16n8k8 tf32 HMMA
// ============================================================================

#define NSP    32768                  // 32*32*32
#define NTILES 512                    // 8 b * 32 t * 2 r-halves
#define GRID   148
#define NTHR   256
#define SMEM_BYTES (28672 * 4)        // 7*64*64 tf32 weights, frag-permuted

// Scratch (__device__ globals: allocation-free rule)
__device__ __align__(16) uint32_t g_xs[8u * NSP * 64];   // 64 MB, tf32 bits
__device__ __align__(16) uint32_t g_bp[7 * 4096];        // 112 KB

__constant__ int c_dt[7] = {0, -1, 1, 0, 0, 0, 0};
__constant__ int c_dr[7] = {0, 0, 0, -1, 1, 0, 0};
__constant__ int c_dc[7] = {0, 0, 0, 0, 0, -1, 1};

static __device__ __forceinline__ uint32_t f2tf32(float v) {
    uint32_t u;
    asm("cvt.rna.tf32.f32 %0, %1;" : "=r"(u) : "f"(v));
    return u;
}

// D(16x8) += A(16x8,row) * B(8x8,col), tf32 inputs, fp32 accumulate
static __device__ __forceinline__ void mma_tf32(
    float* c, uint32_t a0, uint32_t a1, uint32_t a2, uint32_t a3,
    uint32_t b0, uint32_t b1)
{
    asm volatile(
        "mma.sync.aligned.m16n8k8.row.col.f32.tf32.tf32.f32 "
        "{%0,%1,%2,%3}, {%4,%5,%6,%7}, {%8,%9}, {%0,%1,%2,%3};"
        : "+f"(c[0]), "+f"(c[1]), "+f"(c[2]), "+f"(c[3])
        : "r"(a0), "r"(a1), "r"(a2), "r"(a3), "r"(b0), "r"(b1));
}

// ============================================================================
// k_w: Bp[d][kt(8)][n(64)][tg(4)][kk(2)] = tf32( W_d[n][ kt*8 + tg + 4*kk ] )
//   -> per lane (g=lane>>2 picks n, tg=lane&3), one v2 load = (b0, b1)
// ============================================================================
__global__ void k_w(const float* __restrict__ w0, const float* __restrict__ w1,
                    const float* __restrict__ w2, const float* __restrict__ w3,
                    const float* __restrict__ w4, const float* __restrict__ w5,
                    const float* __restrict__ w6)
{
    int i = blockIdx.x * 256 + threadIdx.x;
    if (i >= 7 * 4096) return;
    int d  = i >> 12;
    int kt = (i >> 9) & 7;
    int n  = (i >> 3) & 63;
    int tg = (i >> 1) & 3;
    int kk = i & 1;
    int k  = kt * 8 + tg + 4 * kk;
    const float* w = (d == 0) ? w0 : (d == 1) ? w1 : (d == 2) ? w2 :
                     (d == 3) ? w3 : (d == 4) ? w4 : (d == 5) ? w5 : w6;
    g_bp[i] = f2tf32(w[n * 64 + k]);
}

// ============================================================================
// k_split: g_xs[b][point][jj] , jj = kt*8 + tg*2 + kk  <->  k = kt*8 + tg + 4kk
//   SMEM-transposed 64ch x 64pt tiles; reads & writes fully coalesced.
// ============================================================================
__global__ void __launch_bounds__(256) k_split(const float* __restrict__ x)
{
    __shared__ float sm[64][65];
    int blk = blockIdx.x;                 // 8 b * 512 chunks
    int b   = blk >> 9;
    int nc  = (blk & 511) << 6;
    const float* px = x + (((size_t)b) << 21) + nc;   // x[b][k][n]
    int tid = threadIdx.x;

    #pragma unroll
    for (int i = tid; i < 4096; i += 256) {
        int k = i >> 6, nn = i & 63;
        sm[k][nn] = __ldg(px + (((size_t)k) << 15) + nn);
    }
    __syncthreads();

    uint32_t* po = g_xs + ((((size_t)b << 15) + nc) << 6);
    #pragma unroll
    for (int i = tid; i < 4096; i += 256) {
        int np = i >> 6, jj = i & 63;
        int k  = (jj & ~7) | ((jj >> 1) & 3) | ((jj & 1) << 2);
        po[np * 64 + jj] = f2tf32(sm[k][np]);
    }
}

// ============================================================================
// k_gemm: persistent. Tile = (b, t, 16 r-rows x 32 c) = 512 spatial points.
//   8 warps; warp w owns M=64 (r-rows rbase+2w, +1), N=64, K=64.
//   7 directions accumulate into one 128-reg fp32 accumulator per thread.
//   A: predicated LDG.64 from g_xs (shifted, zero-fill); B: SMEM LDS.64.
// ============================================================================
__global__ void __launch_bounds__(NTHR, 1) k_gemm(float* __restrict__ out)
{
    extern __shared__ uint32_t sB[];    // 112 KB
    const int tid  = threadIdx.x;
    const int w    = tid >> 5;
    const int lane = tid & 31;
    const int g    = lane >> 2;
    const int tg   = lane & 3;

    // stage weights
    #pragma unroll
    for (int i = tid; i < 7168; i += NTHR)
        ((uint4*)sB)[i] = __ldg(((const uint4*)g_bp) + i);
    __syncthreads();

    const uint2* __restrict__ xs2 = (const uint2*)g_xs;

    for (int tile = blockIdx.x; tile < NTILES; tile += GRID) {
        int rq = tile & 1;
        int t  = (tile >> 1) & 31;
        int b  = tile >> 6;
        int rbase = rq * 16 + w * 2;
        int n0 = t * 1024 + rbase * 32;          // warp's m=0 spatial index

        float acc[4][8][4];
        #pragma unroll
        for (int mt = 0; mt < 4; mt++)
            #pragma unroll
            for (int nt = 0; nt < 8; nt++)
                #pragma unroll
                for (int q = 0; q < 4; q++) acc[mt][nt][q] = 0.f;

        #pragma unroll 1
        for (int d = 0; d < 7; ++d) {
            int dt = c_dt[d], dr = c_dr[d], dc = c_dc[d];
            int ts = t + dt;
            if ((unsigned)ts >= 32u) continue;   // t-boundary: contribution = 0

            // per-thread source row pointers (8 point-rows: mt x {g, g+8})
            const uint2* ap[4][2];
            #pragma unroll
            for (int mt = 0; mt < 4; mt++) {
                #pragma unroll
                for (int s = 0; s < 2; s++) {
                    int m  = mt * 16 + g + 8 * s;
                    int rs = rbase + (m >> 5) + dr;
                    int cs = (m & 31) + dc;
                    bool v = ((unsigned)rs < 32u) & ((unsigned)cs < 32u);
                    int nsrc = ts * 1024 + rs * 32 + cs;
                    // uint2 units: point*32 + kt*4 + tg
                    ap[mt][s] = v ? (xs2 + ((((size_t)b << 15) + nsrc) << 5) + tg)
                                  : (const uint2*)0;
                }
            }

            #pragma unroll
            for (int kt = 0; kt < 8; ++kt) {
                uint2 bf[8];
                #pragma unroll
                for (int nt = 0; nt < 8; nt++) {
                    int bi = d * 2048 + kt * 256 + (nt * 8 + g) * 4 + tg;
                    bf[nt] = ((const uint2*)sB)[bi];
                }
                uint2 A0[4], A1[4];
                #pragma unroll
                for (int mt = 0; mt < 4; mt++) {
                    uint2 z; z.x = 0u; z.y = 0u;
                    A0[mt] = ap[mt][0] ? __ldg(ap[mt][0] + kt * 4) : z;
                    A1[mt] = ap[mt][1] ? __ldg(ap[mt][1] + kt * 4) : z;
                }
                #pragma unroll
                for (int mt = 0; mt < 4; mt++)
                    #pragma unroll
                    for (int nt = 0; nt < 8; nt++)
                        mma_tf32(acc[mt][nt],
                                 A0[mt].x, A1[mt].x, A0[mt].y, A1[mt].y,
                                 bf[nt].x, bf[nt].y);
            }
        }

        // epilogue: out[b][o][n0 + m]
        #pragma unroll
        for (int mt = 0; mt < 4; mt++) {
            #pragma unroll
            for (int nt = 0; nt < 8; nt++) {
                int o0 = nt * 8 + tg * 2;
                int m0 = mt * 16 + g;
                float* p = out + ((size_t)(b * 64 + o0) << 15) + n0 + m0;
                p[0]             = acc[mt][nt][0];   // (m0,   o0)
                p[1 << 15]       = acc[mt][nt][1];   // (m0,   o0+1)
                p[8]             = acc[mt][nt][2];   // (m0+8, o0)
                p[(1 << 15) + 8] = acc[mt][nt][3];   // (m0+8, o0+1)
            }
        }
    }
}

// ============================================================================
// Launch
// ============================================================================
extern "C" void kernel_launch(void* const* d_in, const int* in_sizes, int n_in,
                              void* d_out, int out_size)
{
    (void)in_sizes; (void)n_in; (void)out_size;
    static bool attr_done = false;
    if (!attr_done) {
        cudaFuncSetAttribute(k_gemm, cudaFuncAttributeMaxDynamicSharedMemorySize,
                             SMEM_BYTES);
        attr_done = true;
    }

    k_w<<<(7 * 4096 + 255) / 256, 256>>>(
        (const float*)d_in[1], (const float*)d_in[2], (const float*)d_in[3],
        (const float*)d_in[4], (const float*)d_in[5], (const float*)d_in[6],
        (const float*)d_in[7]);

    k_split<<<8 * 512, 256>>>((const float*)d_in[0]);

    k_gemm<<<GRID, NTHR, SMEM_BYTES>>>((float*)d_out);
}

// round 9
// speedup vs baseline: 1.5729x; 1.5729x over previous
#include <cuda_runtime.h>
#include <cuda_fp16.h>
#include <cstdint>

// ============================================================================
// DirectionalConv3d via mma.sync FP16 (compute_103-safe; fp16 mantissa == tf32
// mantissa, so accuracy matches the passing tf32 version at half the traffic
// and half the HMMA count).
//   x: [8, 64, 32, 32, 32] fp32; 7 weights [64,64]; out[b,o,n] =
//     sum_d sum_i W_d[o,i] * x[b,i, n+shift_d]   (zero outside domain)
// Pipeline:
//   k_prep: weights -> fragment-ordered fp16 pairs (g_bp)
//           x -> point-major fragment-permuted fp16 pairs, 128B/pt (g_xh)
//   k_gemm: persistent fused 7-direction GEMM, m16n8k16 f16 HMMA, fp32 accum
// ============================================================================

#define NSP    32768                  // 32*32*32
#define NTILES 512                    // 8 b * 32 t * 2 r-halves
#define GRID   128                    // 4 consecutive tiles per CTA (balanced)
#define NTHR   256
#define SMEM_BYTES (14336 * 4)        // 7*64*64 fp16 weights, frag-permuted

// Scratch (__device__ globals: allocation-free rule)
__device__ __align__(16) uint32_t g_xh[8u * NSP * 32];   // 32 MB fp16 pairs
__device__ __align__(16) uint32_t g_bp[7 * 2048];        // 56 KB fp16 pairs

__constant__ int c_dt[7] = {0, -1, 1, 0, 0, 0, 0};
__constant__ int c_dr[7] = {0, 0, 0, -1, 1, 0, 0};
__constant__ int c_dc[7] = {0, 0, 0, 0, 0, -1, 1};

// D(16x8) += A(16x16,row) * B(16x8,col), fp16 inputs, fp32 accumulate
static __device__ __forceinline__ void mma_f16(
    float* c, uint32_t a0, uint32_t a1, uint32_t a2, uint32_t a3,
    uint32_t b0, uint32_t b1)
{
    asm volatile(
        "mma.sync.aligned.m16n8k16.row.col.f32.f16.f16.f32 "
        "{%0,%1,%2,%3}, {%4,%5,%6,%7}, {%8,%9}, {%0,%1,%2,%3};"
        : "+f"(c[0]), "+f"(c[1]), "+f"(c[2]), "+f"(c[3])
        : "r"(a0), "r"(a1), "r"(a2), "r"(a3), "r"(b0), "r"(b1));
}

static __device__ __forceinline__ uint32_t packh2(float a, float b) {
    __half2 h = __floats2half2_rn(a, b);       // a -> low half, b -> high half
    return *reinterpret_cast<uint32_t*>(&h);
}

// ============================================================================
// k_prep:
//  blocks [0,4096):  x split. Per 64-point chunk: SMEM transpose then emit
//    g_xh[(b*32768+n)*32 + jp], jp = kt*8 + tg*2 + h  <- fp16 pair of source
//    channels (16kt + 2tg + 8h, +1).  Thread fragment load for chunk kt is
//    then one uint2 at pair-slot (kt*4 + tg): {a_k, a_k+8} halves.
//  blocks [4096,4152): weights. g_bp[d*2048 + kt*512 + n*8 + tg*2 + h] =
//    fp16 pair of W_d[n][16kt + 2(tg+4h)], [.. +1].
// ============================================================================
__global__ void __launch_bounds__(256) k_prep(
    const float* __restrict__ x,
    const float* __restrict__ w0, const float* __restrict__ w1,
    const float* __restrict__ w2, const float* __restrict__ w3,
    const float* __restrict__ w4, const float* __restrict__ w5,
    const float* __restrict__ w6)
{
    __shared__ float sm[64][65];
    int blk = blockIdx.x;
    int tid = threadIdx.x;

    if (blk < 4096) {
        int b  = blk >> 9;
        int nc = (blk & 511) << 6;
        const float* px = x + (((size_t)b) << 21) + nc;     // x[b][k][n]
        #pragma unroll
        for (int i = tid; i < 4096; i += 256) {
            int k = i >> 6, nn = i & 63;
            sm[k][nn] = __ldg(px + (((size_t)k) << 15) + nn);
        }
        __syncthreads();
        uint32_t* po = g_xh + ((((size_t)b << 15) + nc) << 5);
        #pragma unroll
        for (int i = tid; i < 2048; i += 256) {
            int np = i >> 5, jp = i & 31;
            int kt = jp >> 3, wv = jp & 7;
            int tg = wv >> 1, h = wv & 1;
            int ks = 16 * kt + 2 * tg + 8 * h;
            po[np * 32 + jp] = packh2(sm[ks][np], sm[ks + 1][np]);
        }
    } else {
        int i = (blk - 4096) * 256 + tid;
        if (i < 14336) {
            int d  = i >> 11;
            int rem = i & 2047;
            int kt = rem >> 9;
            int n  = (rem >> 3) & 63;
            int tg = (rem >> 1) & 3;
            int h  = rem & 1;
            int k  = 16 * kt + 2 * (tg + 4 * h);
            const float* w = (d == 0) ? w0 : (d == 1) ? w1 : (d == 2) ? w2 :
                             (d == 3) ? w3 : (d == 4) ? w4 : (d == 5) ? w5 : w6;
            g_bp[i] = packh2(w[n * 64 + k], w[n * 64 + k + 1]);
        }
    }
}

// ============================================================================
// k_gemm: persistent, 128 CTAs x 4 consecutive tiles.
//   Tile = (b, t, 16 r-rows x 32 c) = 512 spatial points. 8 warps, warp M=64,
//   N=64, K=64 (4 k16 chunks). 7 directions accumulate into one 128-reg fp32
//   accumulator. A: predicated LDG.64 from g_xh (shifted, zero-fill);
//   B: conflict-free LDS.64 from SMEM.
// ============================================================================
__global__ void __launch_bounds__(NTHR, 1) k_gemm(float* __restrict__ out)
{
    extern __shared__ uint32_t sB[];    // 56 KB
    const int tid  = threadIdx.x;
    const int w    = tid >> 5;
    const int lane = tid & 31;
    const int g    = lane >> 2;
    const int tg   = lane & 3;

    // stage weights
    #pragma unroll
    for (int i = tid; i < 3584; i += NTHR)
        ((uint4*)sB)[i] = __ldg(((const uint4*)g_bp) + i);
    __syncthreads();

    const uint2* __restrict__ xs2 = (const uint2*)g_xh;   // 16 uint2 per point

    for (int it = 0; it < 4; ++it) {
        int tile = blockIdx.x * 4 + it;
        int rq = tile & 1;
        int t  = (tile >> 1) & 31;
        int b  = tile >> 6;
        int rbase = rq * 16 + w * 2;
        int n0 = t * 1024 + rbase * 32;          // warp's m=0 spatial index

        float acc[4][8][4];
        #pragma unroll
        for (int mt = 0; mt < 4; mt++)
            #pragma unroll
            for (int nt = 0; nt < 8; nt++)
                #pragma unroll
                for (int q = 0; q < 4; q++) acc[mt][nt][q] = 0.f;

        #pragma unroll 1
        for (int d = 0; d < 7; ++d) {
            int dt = c_dt[d], dr = c_dr[d], dc = c_dc[d];
            int ts = t + dt;
            if ((unsigned)ts >= 32u) continue;   // t-boundary: contribution = 0

            // per-thread source row pointers (8 point-rows: mt x {g, g+8})
            const uint2* ap[4][2];
            #pragma unroll
            for (int mt = 0; mt < 4; mt++) {
                #pragma unroll
                for (int s = 0; s < 2; s++) {
                    int m  = mt * 16 + g + 8 * s;
                    int rs = rbase + (m >> 5) + dr;
                    int cs = (m & 31) + dc;
                    bool v = ((unsigned)rs < 32u) & ((unsigned)cs < 32u);
                    int nsrc = ts * 1024 + rs * 32 + cs;
                    // uint2 units: point*16 + kt*4 + tg
                    ap[mt][s] = v ? (xs2 + ((((size_t)b << 15) + nsrc) << 4) + tg)
                                  : (const uint2*)0;
                }
            }

            #pragma unroll
            for (int kt = 0; kt < 4; ++kt) {
                uint2 bf[8];
                #pragma unroll
                for (int nt = 0; nt < 8; nt++) {
                    // uint2 index: d*1024 + kt*256 + (nt*8+g)*4 + tg
                    int bi = d * 1024 + kt * 256 + (nt * 8 + g) * 4 + tg;
                    bf[nt] = ((const uint2*)sB)[bi];
                }
                uint2 A0[4], A1[4];
                #pragma unroll
                for (int mt = 0; mt < 4; mt++) {
                    uint2 z; z.x = 0u; z.y = 0u;
                    A0[mt] = ap[mt][0] ? __ldg(ap[mt][0] + kt * 4) : z;
                    A1[mt] = ap[mt][1] ? __ldg(ap[mt][1] + kt * 4) : z;
                }
                #pragma unroll
                for (int mt = 0; mt < 4; mt++)
                    #pragma unroll
                    for (int nt = 0; nt < 8; nt++)
                        mma_f16(acc[mt][nt],
                                A0[mt].x, A1[mt].x, A0[mt].y, A1[mt].y,
                                bf[nt].x, bf[nt].y);
            }
        }

        // epilogue: out[b][o][n0 + m]
        #pragma unroll
        for (int mt = 0; mt < 4; mt++) {
            #pragma unroll
            for (int nt = 0; nt < 8; nt++) {
                int o0 = nt * 8 + tg * 2;
                int m0 = mt * 16 + g;
                float* p = out + ((size_t)(b * 64 + o0) << 15) + n0 + m0;
                p[0]             = acc[mt][nt][0];   // (m0,   o0)
                p[1 << 15]       = acc[mt][nt][1];   // (m0,   o0+1)
                p[8]             = acc[mt][nt][2];   // (m0+8, o0)
                p[(1 << 15) + 8] = acc[mt][nt][3];   // (m0+8, o0+1)
            }
        }
    }
}

// ============================================================================
// Launch
// ============================================================================
extern "C" void kernel_launch(void* const* d_in, const int* in_sizes, int n_in,
                              void* d_out, int out_size)
{
    (void)in_sizes; (void)n_in; (void)out_size;
    static bool attr_done = false;
    if (!attr_done) {
        cudaFuncSetAttribute(k_gemm, cudaFuncAttributeMaxDynamicSharedMemorySize,
                             SMEM_BYTES);
        attr_done = true;
    }

    k_prep<<<4096 + 56, 256>>>(
        (const float*)d_in[0],
        (const float*)d_in[1], (const float*)d_in[2], (const float*)d_in[3],
        (const float*)d_in[4], (const float*)d_in[5], (const float*)d_in[6],
        (const float*)d_in[7]);

    k_gemm<<<GRID, NTHR, SMEM_BYTES>>>((float*)d_out);
}

// round 12
// speedup vs baseline: 1.5975x; 1.0156x over previous
#include <cuda_runtime.h>
#include <cuda_fp16.h>
#include <cstdint>

// ============================================================================
// DirectionalConv3d via mma.sync FP16 (compute_103-safe).
//   x: [8, 64, 32, 32, 32] fp32; 7 weights [64,64]; out[b,o,n] =
//     sum_d sum_i W_d[o,i] * x[b,i, n+shift_d]   (zero outside domain)
//
// R9 change vs R8 (85.3us, L1tex=58.8% bound): 8-point-interleaved x layout so
// every A fragment load is one fully-dense LDG.128 (512B contiguous per warp)
// and every B fragment load is one dense LDS.128. Same math, 1/4 the L1
// wavefronts on A, half the load instructions.
//
// x scratch layout (uint4 units):  g_x4[ ((b*4096 + n8)*8 + u)*8 + p ]
//   n8 = n>>3, p = n&7, u = kt2*4 + tg  (kt2 in [0,2): two k16 chunks/uint4)
//   uint4 = { pair(kt=2kt2 ,h=0), pair(kt=2kt2 ,h=1),
//             pair(kt=2kt2+1,h=0), pair(kt=2kt2+1,h=1) }
//   where pair(kt,h) = fp16x2 of channels (16kt + 2tg + 8h, +1)
// B layout (uint4): g_b4[ ((d*2+kt2)*256 + n*4 + tg ]  n = out channel
//   uint4 = { b0(kt=2kt2), b1(kt=2kt2), b0(kt=2kt2+1), b1(kt=2kt2+1) }
//   b0 = fp16x2 of W[n][16kt+2tg], [..+1];  b1 = same at +8.
// ============================================================================

#define NSP    32768
#define NTILES 512                    // 8 b * 32 t * 2 r-halves
#define GRID   128                    // 4 consecutive tiles per CTA
#define NTHR   256
#define SMEM_BYTES (3584 * 16)        // 56 KB weights

__device__ __align__(16) uint4 g_x4[8u * 4096 * 64];   // 32 MB
__device__ __align__(16) uint4 g_b4[3584];             // 56 KB

__constant__ int c_dt[7] = {0, -1, 1, 0, 0, 0, 0};
__constant__ int c_dr[7] = {0, 0, 0, -1, 1, 0, 0};
__constant__ int c_dc[7] = {0, 0, 0, 0, 0, -1, 1};

static __device__ __forceinline__ void mma_f16(
    float* c, uint32_t a0, uint32_t a1, uint32_t a2, uint32_t a3,
    uint32_t b0, uint32_t b1)
{
    asm volatile(
        "mma.sync.aligned.m16n8k16.row.col.f32.f16.f16.f32 "
        "{%0,%1,%2,%3}, {%4,%5,%6,%7}, {%8,%9}, {%0,%1,%2,%3};"
        : "+f"(c[0]), "+f"(c[1]), "+f"(c[2]), "+f"(c[3])
        : "r"(a0), "r"(a1), "r"(a2), "r"(a3), "r"(b0), "r"(b1));
}

static __device__ __forceinline__ uint32_t packh2(float a, float b) {
    __half2 h = __floats2half2_rn(a, b);
    return *reinterpret_cast<uint32_t*>(&h);
}

// ============================================================================
// k_prep: blocks [0,4096) split x (64-point chunks, SMEM transpose);
//         blocks [4096, 4110) permute weights.
// ============================================================================
__global__ void __launch_bounds__(256) k_prep(
    const float* __restrict__ x,
    const float* __restrict__ w0, const float* __restrict__ w1,
    const float* __restrict__ w2, const float* __restrict__ w3,
    const float* __restrict__ w4, const float* __restrict__ w5,
    const float* __restrict__ w6)
{
    __shared__ float sm[64][65];
    int blk = blockIdx.x;
    int tid = threadIdx.x;

    if (blk < 4096) {
        int b  = blk >> 9;
        int nc = (blk & 511) << 6;                     // chunk base point
        const float* px = x + (((size_t)b) << 21) + nc;
        #pragma unroll
        for (int i = tid; i < 4096; i += 256) {
            int k = i >> 6, nn = i & 63;
            sm[k][nn] = __ldg(px + (((size_t)k) << 15) + nn);
        }
        __syncthreads();
        // 512 uint4 per chunk; i = (np>>3)*64 + u*8 + p  (addr-contiguous)
        #pragma unroll
        for (int i = tid; i < 512; i += 256) {
            int p   = i & 7;
            int u   = (i >> 3) & 7;
            int np  = ((i >> 6) << 3) | p;
            int kt2 = u >> 2, tg = u & 3;
            int k0  = 32 * kt2 + 2 * tg;               // kt even base
            int k1  = k0 + 16;                         // kt odd base
            uint4 v;
            v.x = packh2(sm[k0][np],     sm[k0 + 1][np]);
            v.y = packh2(sm[k0 + 8][np], sm[k0 + 9][np]);
            v.z = packh2(sm[k1][np],     sm[k1 + 1][np]);
            v.w = packh2(sm[k1 + 8][np], sm[k1 + 9][np]);
            int n8 = (nc >> 3) + (np >> 3);
            g_x4[((((size_t)b << 12) + n8) << 6) + (u << 3) + p] = v;
        }
    } else {
        int i = (blk - 4096) * 256 + tid;
        if (i < 3584) {
            int d   = i / 512;
            int rem = i & 511;
            int kt2 = rem >> 8;
            int n   = (rem >> 2) & 63;
            int tg  = rem & 3;
            const float* w = (d == 0) ? w0 : (d == 1) ? w1 : (d == 2) ? w2 :
                             (d == 3) ? w3 : (d == 4) ? w4 : (d == 5) ? w5 : w6;
            const float* wr = w + n * 64;
            int k0 = 32 * kt2 + 2 * tg;
            int k1 = k0 + 16;
            uint4 v;
            v.x = packh2(wr[k0],     wr[k0 + 1]);
            v.y = packh2(wr[k0 + 8], wr[k0 + 9]);
            v.z = packh2(wr[k1],     wr[k1 + 1]);
            v.w = packh2(wr[k1 + 8], wr[k1 + 9]);
            g_b4[i] = v;
        }
    }
}

// ============================================================================
// k_gemm: persistent, 128 CTAs x 4 consecutive tiles.
//   Tile = (b, t, 16 r x 32 c) = 512 points; 8 warps, warp M=64 N=64 K=64.
//   A: dense LDG.128 from g_x4 (per-lane boundary predication, zero fill).
//   B: dense LDS.128. 7 directions accumulate in 128 fp32 regs.
// ============================================================================
__global__ void __launch_bounds__(NTHR, 1) k_gemm(float* __restrict__ out)
{
    extern __shared__ uint4 sB[];      // 3584 uint4
    const int tid  = threadIdx.x;
    const int w    = tid >> 5;
    const int lane = tid & 31;
    const int g    = lane >> 2;
    const int tg   = lane & 3;

    #pragma unroll
    for (int i = tid; i < 3584; i += NTHR)
        sB[i] = __ldg(g_b4 + i);
    __syncthreads();

    for (int it = 0; it < 4; ++it) {
        int tile = blockIdx.x * 4 + it;
        int rq = tile & 1;
        int t  = (tile >> 1) & 31;
        int b  = tile >> 6;
        int rbase = rq * 16 + w * 2;
        int n0 = t * 1024 + rbase * 32;

        float acc[4][8][4];
        #pragma unroll
        for (int mt = 0; mt < 4; mt++)
            #pragma unroll
            for (int nt = 0; nt < 8; nt++)
                #pragma unroll
                for (int q = 0; q < 4; q++) acc[mt][nt][q] = 0.f;

        #pragma unroll 1
        for (int d = 0; d < 7; ++d) {
            int dt = c_dt[d], dr = c_dr[d], dc = c_dc[d];
            int ts = t + dt;
            if ((unsigned)ts >= 32u) continue;

            // per-lane uint4 offsets for the 8 A point-rows (mt x {g, g+8})
            unsigned aoff[4][2];
            bool     aval[4][2];
            #pragma unroll
            for (int mt = 0; mt < 4; mt++) {
                #pragma unroll
                for (int s = 0; s < 2; s++) {
                    int m  = mt * 16 + g + 8 * s;
                    int rs = rbase + (m >> 5) + dr;
                    int cs = (m & 31) + dc;
                    bool v = ((unsigned)rs < 32u) & ((unsigned)cs < 32u);
                    int nsrc = ts * 1024 + rs * 32 + cs;
                    aval[mt][s] = v;
                    aoff[mt][s] = (unsigned)((((b << 12) + (nsrc >> 3)) << 6)
                                             + (tg << 3) + (nsrc & 7));
                }
            }

            #pragma unroll
            for (int kt2 = 0; kt2 < 2; ++kt2) {
                uint4 bf[8];
                #pragma unroll
                for (int nt = 0; nt < 8; nt++)
                    bf[nt] = sB[(d * 2 + kt2) * 256 + (nt * 8 + g) * 4 + tg];

                uint4 A0[4], A1[4];
                const uint4 z4 = make_uint4(0u, 0u, 0u, 0u);
                #pragma unroll
                for (int mt = 0; mt < 4; mt++) {
                    A0[mt] = aval[mt][0] ? __ldg(g_x4 + aoff[mt][0] + kt2 * 32) : z4;
                    A1[mt] = aval[mt][1] ? __ldg(g_x4 + aoff[mt][1] + kt2 * 32) : z4;
                }

                #pragma unroll
                for (int mt = 0; mt < 4; mt++)
                    #pragma unroll
                    for (int nt = 0; nt < 8; nt++) {
                        mma_f16(acc[mt][nt], A0[mt].x, A1[mt].x, A0[mt].y, A1[mt].y,
                                bf[nt].x, bf[nt].y);
                        mma_f16(acc[mt][nt], A0[mt].z, A1[mt].z, A0[mt].w, A1[mt].w,
                                bf[nt].z, bf[nt].w);
                    }
            }
        }

        // epilogue: out[b][o][n0 + m]
        #pragma unroll
        for (int mt = 0; mt < 4; mt++) {
            #pragma unroll
            for (int nt = 0; nt < 8; nt++) {
                int o0 = nt * 8 + tg * 2;
                int m0 = mt * 16 + g;
                float* p = out + ((size_t)(b * 64 + o0) << 15) + n0 + m0;
                p[0]             = acc[mt][nt][0];
                p[1 << 15]       = acc[mt][nt][1];
                p[8]             = acc[mt][nt][2];
                p[(1 << 15) + 8] = acc[mt][nt][3];
            }
        }
    }
}

// ============================================================================
// Launch
// ============================================================================
extern "C" void kernel_launch(void* const* d_in, const int* in_sizes, int n_in,
                              void* d_out, int out_size)
{
    (void)in_sizes; (void)n_in; (void)out_size;
    static bool attr_done = false;
    if (!attr_done) {
        cudaFuncSetAttribute(k_gemm, cudaFuncAttributeMaxDynamicSharedMemorySize,
                             SMEM_BYTES);
        attr_done = true;
    }

    k_prep<<<4096 + 14, 256>>>(
        (const float*)d_in[0],
        (const float*)d_in[1], (const float*)d_in[2], (const float*)d_in[3],
        (const float*)d_in[4], (const float*)d_in[5], (const float*)d_in[6],
        (const float*)d_in[7]);

    k_gemm<<<GRID, NTHR, SMEM_BYTES>>>((float*)d_out);
}